// round 3
// baseline (speedup 1.0000x reference)
#include <cuda_runtime.h>
#include <cuda_bf16.h>
#include <cstdint>

// ---------------- scratch (static device allocations only) ----------------
#define MAXN 100000
__device__ float g_deg[MAXN];                 // deg, then dinv
__device__ float g_xa[(size_t)MAXN * 128];    // agg(x) (+self), later LN output
__device__ float g_h1[(size_t)MAXN * 256];    // pre-BN hidden
__device__ float g_t [(size_t)MAXN * 128];    // h1' @ W2
__device__ float g_h2[(size_t)MAXN * 128];    // agg(t)
__device__ float g_z [(size_t)MAXN * 128];    // final embeddings
__device__ float g_bnsum[256];
__device__ float g_bnsumsq[256];
__device__ float g_bnsc[256];
__device__ float g_bnsh[256];

// ---------------- small kernels ----------------
__global__ void deg_kernel(float* __restrict__ deg, const int* __restrict__ dst, int E) {
    int i = blockIdx.x * blockDim.x + threadIdx.x;
    if (i < E) atomicAdd(&deg[dst[i]], 1.0f);
}

__global__ void dinv_kernel(float* __restrict__ deg, int N) {
    int i = blockIdx.x * blockDim.x + threadIdx.x;
    if (i < N) deg[i] = rsqrtf(deg[i] + 1.0f);
}

// one warp per edge, 128 features (32 lanes x float4), vector red to dst row
__global__ void agg_kernel(const float* __restrict__ feat, float* __restrict__ out,
                           const int* __restrict__ src, const int* __restrict__ dst, int E,
                           const float* __restrict__ dinv) {
    int w = (blockIdx.x * blockDim.x + threadIdx.x) >> 5;
    int lane = threadIdx.x & 31;
    if (w >= E) return;
    int s = src[w];
    int d = dst[w];
    float coef = dinv[s] * dinv[d];
    float4 v = *(const float4*)(feat + (size_t)s * 128 + lane * 4);
    v.x *= coef; v.y *= coef; v.z *= coef; v.w *= coef;
    float* p = out + (size_t)d * 128 + lane * 4;
    asm volatile("red.global.add.v4.f32 [%0], {%1,%2,%3,%4};"
                 :: "l"(p), "f"(v.x), "f"(v.y), "f"(v.z), "f"(v.w) : "memory");
}

// xa[i] += x[i] * dinv[i]^2   (self-loop term, layer 1)
__global__ void selfloop_kernel(const float* __restrict__ x, const float* __restrict__ dinv,
                                float* __restrict__ xa, int N) {
    int i = blockIdx.x * blockDim.x + threadIdx.x;
    if (i >= N * 32) return;
    int row = i >> 5, l = i & 31;
    float di = dinv[row];
    float c = di * di;
    size_t base = (size_t)row * 128 + l * 4;
    float4 v = *(const float4*)(x + base);
    float4 a = *(const float4*)(xa + base);
    a.x += v.x * c; a.y += v.y * c; a.z += v.z * c; a.w += v.w * c;
    *(float4*)(xa + base) = a;
}

// column sums / sumsq over h1 [N,256]
__global__ void colstats_kernel(const float* __restrict__ h, float* __restrict__ sum,
                                float* __restrict__ sumsq, int N) {
    int c = threadIdx.x;                 // 256 threads = 256 columns
    int r0 = blockIdx.x * 256;
    int r1 = min(r0 + 256, N);
    float s = 0.f, s2 = 0.f;
    for (int r = r0; r < r1; r++) {
        float v = h[(size_t)r * 256 + c];
        s += v;
        s2 = fmaf(v, v, s2);
    }
    atomicAdd(&sum[c], s);
    atomicAdd(&sumsq[c], s2);
}

__global__ void bnfinal_kernel(const float* __restrict__ sum, const float* __restrict__ sumsq,
                               const float* __restrict__ gamma, const float* __restrict__ beta,
                               float* __restrict__ sc, float* __restrict__ sh, int N) {
    int c = threadIdx.x;
    float invN = 1.0f / (float)N;
    float mu = sum[c] * invN;
    float var = fmaxf(sumsq[c] * invN - mu * mu, 0.f);
    float scv = gamma[c] * rsqrtf(var + 1e-5f);
    sc[c] = scv;
    sh[c] = beta[c] - mu * scv;
}

// per-node: v = agg + t*dinv^2 + b2 ; LayerNorm ; relu -> out. one warp per row.
__global__ void ln_kernel(const float* __restrict__ agg, const float* __restrict__ t,
                          const float* __restrict__ dinv, const float* __restrict__ b2,
                          const float* __restrict__ lng, const float* __restrict__ lnb,
                          float* __restrict__ out, int N) {
    int w = (blockIdx.x * blockDim.x + threadIdx.x) >> 5;
    int lane = threadIdx.x & 31;
    if (w >= N) return;
    float di = dinv[w];
    float c = di * di;
    size_t base = (size_t)w * 128 + lane * 4;
    float4 a = *(const float4*)(agg + base);
    float4 tv = *(const float4*)(t + base);
    float4 bb = *(const float4*)(b2 + lane * 4);
    float4 v;
    v.x = fmaf(tv.x, c, a.x) + bb.x;
    v.y = fmaf(tv.y, c, a.y) + bb.y;
    v.z = fmaf(tv.z, c, a.z) + bb.z;
    v.w = fmaf(tv.w, c, a.w) + bb.w;
    float s = v.x + v.y + v.z + v.w;
    #pragma unroll
    for (int off = 16; off; off >>= 1) s += __shfl_xor_sync(0xffffffffu, s, off);
    float mu = s * (1.0f / 128.0f);
    float dx = v.x - mu, dy = v.y - mu, dz = v.z - mu, dw = v.w - mu;
    float q = dx * dx + dy * dy + dz * dz + dw * dw;
    #pragma unroll
    for (int off = 16; off; off >>= 1) q += __shfl_xor_sync(0xffffffffu, q, off);
    float rs = rsqrtf(q * (1.0f / 128.0f) + 1e-5f);
    float4 g = *(const float4*)(lng + lane * 4);
    float4 bo = *(const float4*)(lnb + lane * 4);
    float4 o;
    o.x = fmaxf(fmaf(dx * rs, g.x, bo.x), 0.f);
    o.y = fmaxf(fmaf(dy * rs, g.y, bo.y), 0.f);
    o.z = fmaxf(fmaf(dz * rs, g.z, bo.z), 0.f);
    o.w = fmaxf(fmaf(dw * rs, g.w, bo.w), 0.f);
    *(float4*)(out + base) = o;
}

// decode: one warp per pair, dot over 128 feats
__global__ void decode_kernel(const float* __restrict__ z, const int* __restrict__ ia,
                              const int* __restrict__ ib,
                              const float* __restrict__ cutoff, float* __restrict__ out,
                              int EL, int writeRound) {
    int w = (blockIdx.x * blockDim.x + threadIdx.x) >> 5;
    int lane = threadIdx.x & 31;
    if (w >= EL) return;
    int a = ia[w];
    int b = ib[w];
    float4 za = *(const float4*)(z + (size_t)a * 128 + lane * 4);
    float4 zb = *(const float4*)(z + (size_t)b * 128 + lane * 4);
    float s = za.x * zb.x + za.y * zb.y + za.z * zb.z + za.w * zb.w;
    #pragma unroll
    for (int off = 16; off; off >>= 1) s += __shfl_xor_sync(0xffffffffu, s, off);
    if (lane == 0) {
        out[w] = s;
        if (writeRound) out[(size_t)EL + w] = (s < cutoff[0]) ? 0.0f : 1.0f;
    }
}

// ---------------- SIMT fp32 GEMM: C[N,M] = op(A)[N,K] @ B[K,M] (+bias) ----------------
// ATRANS=1: a' = relu(a*ksc[k] + ksh[k])  (fused BatchNorm+ReLU on the A operand)
template<int ATRANS>
__global__ void __launch_bounds__(256, 2) gemm_kernel(
    const float* __restrict__ A, const float* __restrict__ B,
    const float* __restrict__ bias, float* __restrict__ C,
    int Nrows, int K, int M,
    const float* __restrict__ ksc, const float* __restrict__ ksh) {
    __shared__ float As[16][132];
    __shared__ float Bs[16][128];
    int tid = threadIdx.x;
    int tx = tid & 15, ty = tid >> 4;
    int rowBase = blockIdx.y * 128;
    int colBase = blockIdx.x * 128;
    float acc[8][8];
    #pragma unroll
    for (int i = 0; i < 8; i++)
        #pragma unroll
        for (int j = 0; j < 8; j++) acc[i][j] = 0.f;

    int aRow = tid >> 2;
    int aK = (tid & 3) << 2;
    int bK = tid >> 5;
    int bN = (tid & 31) << 2;

    for (int k0 = 0; k0 < K; k0 += 16) {
        #pragma unroll
        for (int i = 0; i < 2; i++) {
            int r = aRow + i * 64;
            int grow = rowBase + r;
            float4 v = make_float4(0.f, 0.f, 0.f, 0.f);
            if (grow < Nrows) v = *(const float4*)(A + (size_t)grow * K + k0 + aK);
            if (ATRANS) {
                int kg = k0 + aK;
                v.x = fmaxf(fmaf(v.x, ksc[kg + 0], ksh[kg + 0]), 0.f);
                v.y = fmaxf(fmaf(v.y, ksc[kg + 1], ksh[kg + 1]), 0.f);
                v.z = fmaxf(fmaf(v.z, ksc[kg + 2], ksh[kg + 2]), 0.f);
                v.w = fmaxf(fmaf(v.w, ksc[kg + 3], ksh[kg + 3]), 0.f);
            }
            As[aK + 0][r] = v.x; As[aK + 1][r] = v.y;
            As[aK + 2][r] = v.z; As[aK + 3][r] = v.w;
        }
        #pragma unroll
        for (int i = 0; i < 2; i++) {
            int kk = bK + i * 8;
            *(float4*)&Bs[kk][bN] = *(const float4*)(B + (size_t)(k0 + kk) * M + colBase + bN);
        }
        __syncthreads();
        #pragma unroll
        for (int k = 0; k < 16; k++) {
            float4 a0 = *(float4*)&As[k][ty * 8];
            float4 a1 = *(float4*)&As[k][ty * 8 + 4];
            float4 b0 = *(float4*)&Bs[k][tx * 8];
            float4 b1 = *(float4*)&Bs[k][tx * 8 + 4];
            float ra[8] = {a0.x, a0.y, a0.z, a0.w, a1.x, a1.y, a1.z, a1.w};
            float rb[8] = {b0.x, b0.y, b0.z, b0.w, b1.x, b1.y, b1.z, b1.w};
            #pragma unroll
            for (int i = 0; i < 8; i++)
                #pragma unroll
                for (int j = 0; j < 8; j++)
                    acc[i][j] = fmaf(ra[i], rb[j], acc[i][j]);
        }
        __syncthreads();
    }
    #pragma unroll
    for (int i = 0; i < 8; i++) {
        int grow = rowBase + ty * 8 + i;
        if (grow >= Nrows) break;   // rows for this thread are consecutive
        #pragma unroll
        for (int j = 0; j < 8; j += 4) {
            int gcol = colBase + tx * 8 + j;
            float4 o;
            o.x = acc[i][j]; o.y = acc[i][j + 1]; o.z = acc[i][j + 2]; o.w = acc[i][j + 3];
            if (bias) {
                o.x += bias[gcol]; o.y += bias[gcol + 1];
                o.z += bias[gcol + 2]; o.w += bias[gcol + 3];
            }
            *(float4*)(C + (size_t)grow * M + gcol) = o;
        }
    }
}

// ---------------- launch ----------------
extern "C" void kernel_launch(void* const* d_in, const int* in_sizes, int n_in,
                              void* d_out, int out_size) {
    const float* x    = (const float*)d_in[0];
    const int*   ei   = (const int*)d_in[1];   // [2, E] int32 (JAX x64 disabled)
    const int*   eli  = (const int*)d_in[2];   // [2, EL] int32
    const float* cut  = (const float*)d_in[3];
    const float* W1   = (const float*)d_in[4];
    const float* b1   = (const float*)d_in[5];
    const float* bng  = (const float*)d_in[6];
    const float* bnb  = (const float*)d_in[7];
    const float* W2   = (const float*)d_in[8];
    const float* b2   = (const float*)d_in[9];
    const float* lng  = (const float*)d_in[10];
    const float* lnb  = (const float*)d_in[11];
    const float* linW = (const float*)d_in[12];
    const float* linb = (const float*)d_in[13];

    int N  = in_sizes[0] / 128;
    int E  = in_sizes[1] / 2;
    int EL = in_sizes[2] / 2;
    const int* src = ei;
    const int* dst = ei + E;
    const int* la  = eli;
    const int* lb  = eli + EL;
    float* out = (float*)d_out;

    void *p_deg, *p_xa, *p_h1, *p_t, *p_h2, *p_z, *p_sum, *p_sumsq, *p_sc, *p_sh;
    cudaGetSymbolAddress(&p_deg,   g_deg);
    cudaGetSymbolAddress(&p_xa,    g_xa);
    cudaGetSymbolAddress(&p_h1,    g_h1);
    cudaGetSymbolAddress(&p_t,     g_t);
    cudaGetSymbolAddress(&p_h2,    g_h2);
    cudaGetSymbolAddress(&p_z,     g_z);
    cudaGetSymbolAddress(&p_sum,   g_bnsum);
    cudaGetSymbolAddress(&p_sumsq, g_bnsumsq);
    cudaGetSymbolAddress(&p_sc,    g_bnsc);
    cudaGetSymbolAddress(&p_sh,    g_bnsh);

    float* deg  = (float*)p_deg;
    float* xa   = (float*)p_xa;
    float* h1   = (float*)p_h1;
    float* t    = (float*)p_t;
    float* h2   = (float*)p_h2;
    float* z    = (float*)p_z;
    float* bsum = (float*)p_sum;
    float* bsq  = (float*)p_sumsq;
    float* bsc  = (float*)p_sc;
    float* bsh  = (float*)p_sh;

    cudaMemsetAsync(deg, 0, (size_t)N * sizeof(float));
    cudaMemsetAsync(xa,  0, (size_t)N * 128 * sizeof(float));
    cudaMemsetAsync(h2,  0, (size_t)N * 128 * sizeof(float));
    cudaMemsetAsync(bsum, 0, 256 * sizeof(float));
    cudaMemsetAsync(bsq,  0, 256 * sizeof(float));

    // degree + dinv
    deg_kernel<<<(E + 255) / 256, 256>>>(deg, dst, E);
    dinv_kernel<<<(N + 255) / 256, 256>>>(deg, N);

    // layer 1: aggregate x (128 feats), then GEMM
    agg_kernel<<<(E + 7) / 8, 256>>>(x, xa, src, dst, E, deg);
    selfloop_kernel<<<((size_t)N * 32 + 255) / 256, 256>>>(x, deg, xa, N);
    gemm_kernel<0><<<dim3(2, (N + 127) / 128), 256>>>(xa, W1, b1, h1, N, 128, 256, nullptr, nullptr);

    // BatchNorm stats
    colstats_kernel<<<(N + 255) / 256, 256>>>(h1, bsum, bsq, N);
    bnfinal_kernel<<<1, 256>>>(bsum, bsq, bng, bnb, bsc, bsh, N);

    // layer 2: GEMM with fused BN+ReLU on A, then aggregate
    gemm_kernel<1><<<dim3(1, (N + 127) / 128), 256>>>(h1, W2, nullptr, t, N, 256, 128, bsc, bsh);
    agg_kernel<<<(E + 7) / 8, 256>>>(t, h2, src, dst, E, deg);

    // self-loop + bias + LayerNorm + ReLU -> xa (reused as GEMM3 input)
    ln_kernel<<<((size_t)N * 32 + 255) / 256, 256>>>(h2, t, deg, b2, lng, lnb, xa, N);

    // final linear
    gemm_kernel<0><<<dim3(1, (N + 127) / 128), 256>>>(xa, linW, linb, z, N, 128, 128, nullptr, nullptr);

    // decode
    int writeRound = (out_size >= 2 * EL) ? 1 : 0;
    decode_kernel<<<((size_t)EL + 7) / 8, 256>>>(z, la, lb, cut, out, EL, writeRound);
}

// round 6
// speedup vs baseline: 1.1913x; 1.1913x over previous
#include <cuda_runtime.h>
#include <cuda_bf16.h>
#include <cstdint>

// ============================ helpers ============================
__device__ __forceinline__ float tf32rnd(float x) {
    uint32_t o; asm("cvt.rna.tf32.f32 %0, %1;" : "=r"(o) : "f"(x)); return __uint_as_float(o);
}
__device__ __forceinline__ uint32_t smem_u32(const void* p) {
    uint32_t a;
    asm("{ .reg .u64 t; cvta.to.shared.u64 t, %1; cvt.u32.u64 %0, t; }" : "=r"(a) : "l"(p));
    return a;
}
#define LDSM_X4(r0, r1, r2, r3, addr) \
    asm volatile("ldmatrix.sync.aligned.m8n8.x4.shared.b16 {%0,%1,%2,%3}, [%4];" \
                 : "=r"(r0), "=r"(r1), "=r"(r2), "=r"(r3) : "r"(addr))
#define MMA_TF32(d, a0, a1, a2, a3, b0, b1) \
    asm volatile("mma.sync.aligned.m16n8k8.row.col.f32.tf32.tf32.f32 " \
                 "{%0,%1,%2,%3},{%4,%5,%6,%7},{%8,%9},{%0,%1,%2,%3};" \
                 : "+f"(d[0]), "+f"(d[1]), "+f"(d[2]), "+f"(d[3]) \
                 : "r"(a0), "r"(a1), "r"(a2), "r"(a3), "r"(b0), "r"(b1))

// ============================ scratch ============================
#define MAXN 100000
__device__ float g_deg[MAXN];
__device__ float g_xa[(size_t)MAXN * 128];
__device__ float g_h1[(size_t)MAXN * 256];
__device__ float g_t [(size_t)MAXN * 128];
__device__ float g_h2[(size_t)MAXN * 128];
__device__ float g_z [(size_t)MAXN * 128];
__device__ float g_bnsum[256];
__device__ float g_bnsumsq[256];
__device__ float g_bnsc[256];
__device__ float g_bnsh[256];
// pre-split transposed weights: [NOUT][K] hi/lo, K-major rows
__device__ float g_w1t_hi[256 * 128];
__device__ float g_w1t_lo[256 * 128];
__device__ float g_w2t_hi[128 * 256];
__device__ float g_w2t_lo[128 * 256];
__device__ float g_w3t_hi[128 * 128];
__device__ float g_w3t_lo[128 * 128];

// ============================ small kernels ============================
__global__ void deg_kernel(float* __restrict__ deg, const int* __restrict__ dst, int E) {
    int i = blockIdx.x * blockDim.x + threadIdx.x;
    if (i < E) atomicAdd(&deg[dst[i]], 1.0f);
}
__global__ void dinv_kernel(float* __restrict__ deg, int N) {
    int i = blockIdx.x * blockDim.x + threadIdx.x;
    if (i < N) deg[i] = rsqrtf(deg[i] + 1.0f);
}
__global__ void wsplit_kernel(const float* __restrict__ W, float* __restrict__ hiT,
                              float* __restrict__ loT, int K, int NOUT) {
    int i = blockIdx.x * blockDim.x + threadIdx.x;
    if (i >= K * NOUT) return;
    int k = i / NOUT, n = i % NOUT;
    float x = W[i];
    float h = tf32rnd(x);
    float l = tf32rnd(x - h);
    hiT[(size_t)n * K + k] = h;
    loT[(size_t)n * K + k] = l;
}
__global__ void agg_kernel(const float* __restrict__ feat, float* __restrict__ out,
                           const int* __restrict__ src, const int* __restrict__ dst, int E,
                           const float* __restrict__ dinv) {
    int w = (blockIdx.x * blockDim.x + threadIdx.x) >> 5;
    int lane = threadIdx.x & 31;
    if (w >= E) return;
    int s = src[w];
    int d = dst[w];
    float coef = dinv[s] * dinv[d];
    float4 v = *(const float4*)(feat + (size_t)s * 128 + lane * 4);
    v.x *= coef; v.y *= coef; v.z *= coef; v.w *= coef;
    float* p = out + (size_t)d * 128 + lane * 4;
    asm volatile("red.global.add.v4.f32 [%0], {%1,%2,%3,%4};"
                 :: "l"(p), "f"(v.x), "f"(v.y), "f"(v.z), "f"(v.w) : "memory");
}
__global__ void selfloop_kernel(const float* __restrict__ x, const float* __restrict__ dinv,
                                float* __restrict__ xa, int N) {
    int i = blockIdx.x * blockDim.x + threadIdx.x;
    if (i >= N * 32) return;
    int row = i >> 5, l = i & 31;
    float di = dinv[row];
    float c = di * di;
    size_t base = (size_t)row * 128 + l * 4;
    float4 v = *(const float4*)(x + base);
    float4 a = *(const float4*)(xa + base);
    a.x += v.x * c; a.y += v.y * c; a.z += v.z * c; a.w += v.w * c;
    *(float4*)(xa + base) = a;
}
__global__ void colstats_kernel(const float* __restrict__ h, float* __restrict__ sum,
                                float* __restrict__ sumsq, int N) {
    int c = threadIdx.x;
    int r0 = blockIdx.x * 256;
    int r1 = min(r0 + 256, N);
    float s = 0.f, s2 = 0.f;
    for (int r = r0; r < r1; r++) {
        float v = h[(size_t)r * 256 + c];
        s += v;
        s2 = fmaf(v, v, s2);
    }
    atomicAdd(&sum[c], s);
    atomicAdd(&sumsq[c], s2);
}
__global__ void bnfinal_kernel(const float* __restrict__ sum, const float* __restrict__ sumsq,
                               const float* __restrict__ gamma, const float* __restrict__ beta,
                               float* __restrict__ sc, float* __restrict__ sh, int N) {
    int c = threadIdx.x;
    float invN = 1.0f / (float)N;
    float mu = sum[c] * invN;
    float var = fmaxf(sumsq[c] * invN - mu * mu, 0.f);
    float scv = gamma[c] * rsqrtf(var + 1e-5f);
    sc[c] = scv;
    sh[c] = beta[c] - mu * scv;
}
__global__ void ln_kernel(const float* __restrict__ agg, const float* __restrict__ t,
                          const float* __restrict__ dinv, const float* __restrict__ b2,
                          const float* __restrict__ lng, const float* __restrict__ lnb,
                          float* __restrict__ out, int N) {
    int w = (blockIdx.x * blockDim.x + threadIdx.x) >> 5;
    int lane = threadIdx.x & 31;
    if (w >= N) return;
    float di = dinv[w];
    float c = di * di;
    size_t base = (size_t)w * 128 + lane * 4;
    float4 a = *(const float4*)(agg + base);
    float4 tv = *(const float4*)(t + base);
    float4 bb = *(const float4*)(b2 + lane * 4);
    float4 v;
    v.x = fmaf(tv.x, c, a.x) + bb.x;
    v.y = fmaf(tv.y, c, a.y) + bb.y;
    v.z = fmaf(tv.z, c, a.z) + bb.z;
    v.w = fmaf(tv.w, c, a.w) + bb.w;
    float s = v.x + v.y + v.z + v.w;
    #pragma unroll
    for (int off = 16; off; off >>= 1) s += __shfl_xor_sync(0xffffffffu, s, off);
    float mu = s * (1.0f / 128.0f);
    float dx = v.x - mu, dy = v.y - mu, dz = v.z - mu, dw = v.w - mu;
    float q = dx * dx + dy * dy + dz * dz + dw * dw;
    #pragma unroll
    for (int off = 16; off; off >>= 1) q += __shfl_xor_sync(0xffffffffu, q, off);
    float rs = rsqrtf(q * (1.0f / 128.0f) + 1e-5f);
    float4 g = *(const float4*)(lng + lane * 4);
    float4 bo = *(const float4*)(lnb + lane * 4);
    float4 o;
    o.x = fmaxf(fmaf(dx * rs, g.x, bo.x), 0.f);
    o.y = fmaxf(fmaf(dy * rs, g.y, bo.y), 0.f);
    o.z = fmaxf(fmaf(dz * rs, g.z, bo.z), 0.f);
    o.w = fmaxf(fmaf(dw * rs, g.w, bo.w), 0.f);
    *(float4*)(out + base) = o;
}
__global__ void decode_kernel(const float* __restrict__ z, const int* __restrict__ ia,
                              const int* __restrict__ ib,
                              const float* __restrict__ cutoff, float* __restrict__ out,
                              int EL, int writeRound) {
    int w = (blockIdx.x * blockDim.x + threadIdx.x) >> 5;
    int lane = threadIdx.x & 31;
    if (w >= EL) return;
    int a = ia[w];
    int b = ib[w];
    float4 za = *(const float4*)(z + (size_t)a * 128 + lane * 4);
    float4 zb = *(const float4*)(z + (size_t)b * 128 + lane * 4);
    float s = za.x * zb.x + za.y * zb.y + za.z * zb.z + za.w * zb.w;
    #pragma unroll
    for (int off = 16; off; off >>= 1) s += __shfl_xor_sync(0xffffffffu, s, off);
    if (lane == 0) {
        out[w] = s;
        if (writeRound) out[(size_t)EL + w] = (s < cutoff[0]) ? 0.0f : 1.0f;
    }
}

// ============================ mma.sync tf32x3 GEMM ============================
// C[Nrows, ldC] tile (128 x 128 per CTA): C = op(A)[Nrows,K] @ BT^T
// BT pre-split hi/lo, [NOUT][K] K-major.  FUSE: a' = relu(a*sc[k]+sh[k]).
// 8 warps: 2 (M) x 4 (N), warp tile 64x32, mma.m16n8k8 tf32, tf32x3 split.
template<int K, bool FUSE, bool HASBIAS>
__global__ void __launch_bounds__(256, 2)
mm_gemm_kernel(const float* __restrict__ A,
               const float* __restrict__ BTh, const float* __restrict__ BTl,
               const float* __restrict__ bias,
               const float* __restrict__ sc, const float* __restrict__ sh,
               float* __restrict__ C, int Nrows, int ldC) {
    constexpr int NC  = K / 32;       // k-chunks of 32
    constexpr int PAD = 36;           // floats per padded row
    constexpr int ASZ = 128 * PAD * 4;  // bytes per copy (A==B size)

    extern __shared__ char smem[];
    float* sAh = (float*)(smem);
    float* sAl = (float*)(smem + ASZ);
    float* sBh = (float*)(smem + 2 * ASZ);
    float* sBl = (float*)(smem + 3 * ASZ);

    int tid = threadIdx.x, lane = tid & 31, warp = tid >> 5;
    int warpM = warp & 1, warpN = warp >> 1;
    int rowBase  = blockIdx.x * 128;
    int colBaseG = blockIdx.y * 128;

    float acc[4][4][4];
    #pragma unroll
    for (int i = 0; i < 4; i++)
        #pragma unroll
        for (int j = 0; j < 4; j++)
            #pragma unroll
            for (int r = 0; r < 4; r++) acc[i][j][r] = 0.f;

    // loader indices: each thread owns (row = tid/2, k-half = (tid&1)*16)
    int larow  = tid >> 1;
    int lkhalf = (tid & 1) * 16;
    bool rOK = (rowBase + larow) < Nrows;
    const float* aRow  = A   + (size_t)(rowBase + larow) * K + lkhalf;
    const float* bRowH = BTh + (size_t)(colBaseG + larow) * K + lkhalf;
    const float* bRowL = BTl + (size_t)(colBaseG + larow) * K + lkhalf;
    float* sAhp = sAh + larow * PAD + lkhalf;
    float* sAlp = sAl + larow * PAD + lkhalf;
    float* sBhp = sBh + larow * PAD + lkhalf;
    float* sBlp = sBl + larow * PAD + lkhalf;

    // ldmatrix per-lane addresses
    int al_r = (lane & 7) + (lane & 8);          // row within 16-row frag
    int al_k = (lane & 16) >> 2;                 // +4 cols if lane>=16
    uint32_t aHbase = smem_u32(sAh) + (uint32_t)(((warpM * 64 + al_r) * PAD + al_k) << 2);
    uint32_t aLbase = aHbase + ASZ;
    int bl_n = (lane & 7) + ((lane & 16) >> 1);  // n within 16-col pair
    int bl_k = (lane & 8) >> 1;                  // +4 if bit3
    uint32_t bHbase = smem_u32(sBh) + (uint32_t)(((warpN * 32 + bl_n) * PAD + bl_k) << 2);
    uint32_t bLbase = bHbase + ASZ;

    for (int c = 0; c < NC; c++) {
        int k0 = c * 32;
        __syncthreads();   // previous chunk's mma reads done
        // ---- A: load 16 floats, fuse, split hi/lo, store
        {
            const float4* ap = (const float4*)(aRow + k0);
            #pragma unroll
            for (int j = 0; j < 4; j++) {
                float4 v = rOK ? ap[j] : make_float4(0.f, 0.f, 0.f, 0.f);
                if (FUSE) {
                    int kg = k0 + lkhalf + j * 4;
                    float4 s4 = *(const float4*)(sc + kg);
                    float4 h4 = *(const float4*)(sh + kg);
                    v.x = fmaxf(fmaf(v.x, s4.x, h4.x), 0.f);
                    v.y = fmaxf(fmaf(v.y, s4.y, h4.y), 0.f);
                    v.z = fmaxf(fmaf(v.z, s4.z, h4.z), 0.f);
                    v.w = fmaxf(fmaf(v.w, s4.w, h4.w), 0.f);
                }
                float4 hi, lo;
                hi.x = tf32rnd(v.x); lo.x = tf32rnd(v.x - hi.x);
                hi.y = tf32rnd(v.y); lo.y = tf32rnd(v.y - hi.y);
                hi.z = tf32rnd(v.z); lo.z = tf32rnd(v.z - hi.z);
                hi.w = tf32rnd(v.w); lo.w = tf32rnd(v.w - hi.w);
                *(float4*)(sAhp + j * 4) = hi;
                *(float4*)(sAlp + j * 4) = lo;
            }
        }
        // ---- B: straight copies of pre-split weights
        {
            const float4* bh = (const float4*)(bRowH + k0);
            const float4* bl = (const float4*)(bRowL + k0);
            #pragma unroll
            for (int j = 0; j < 4; j++) *(float4*)(sBhp + j * 4) = bh[j];
            #pragma unroll
            for (int j = 0; j < 4; j++) *(float4*)(sBlp + j * 4) = bl[j];
        }
        __syncthreads();

        // ---- compute: 4 k8 steps
        #pragma unroll
        for (int s = 0; s < 4; s++) {
            uint32_t koff = (uint32_t)(s * 8 * 4);
            uint32_t bh[2][4], bl[2][4];
            #pragma unroll
            for (int p = 0; p < 2; p++) {
                uint32_t po = (uint32_t)(p * 16 * PAD * 4);
                LDSM_X4(bh[p][0], bh[p][1], bh[p][2], bh[p][3], bHbase + po + koff);
                LDSM_X4(bl[p][0], bl[p][1], bl[p][2], bl[p][3], bLbase + po + koff);
            }
            #pragma unroll
            for (int i = 0; i < 4; i++) {
                uint32_t io = (uint32_t)(i * 16 * PAD * 4);
                uint32_t ah0, ah1, ah2, ah3, alo0, alo1, alo2, alo3;
                LDSM_X4(ah0, ah1, ah2, ah3, aHbase + io + koff);
                LDSM_X4(alo0, alo1, alo2, alo3, aLbase + io + koff);
                #pragma unroll
                for (int j = 0; j < 4; j++) {
                    int p = j >> 1, o = (j & 1) * 2;
                    MMA_TF32(acc[i][j], ah0, ah1, ah2, ah3, bh[p][o], bh[p][o + 1]);
                    MMA_TF32(acc[i][j], ah0, ah1, ah2, ah3, bl[p][o], bl[p][o + 1]);
                    MMA_TF32(acc[i][j], alo0, alo1, alo2, alo3, bh[p][o], bh[p][o + 1]);
                }
            }
        }
    }

    // ---- epilogue
    int gid = lane >> 2, tc2 = (lane & 3) * 2;
    #pragma unroll
    for (int i = 0; i < 4; i++) {
        int r0 = rowBase + warpM * 64 + i * 16 + gid;
        int r1 = r0 + 8;
        #pragma unroll
        for (int j = 0; j < 4; j++) {
            int col = colBaseG + warpN * 32 + j * 8 + tc2;
            float bx = 0.f, by = 0.f;
            if (HASBIAS) { bx = bias[col]; by = bias[col + 1]; }
            if (r0 < Nrows) {
                float2 v = make_float2(acc[i][j][0] + bx, acc[i][j][1] + by);
                *(float2*)(C + (size_t)r0 * ldC + col) = v;
            }
            if (r1 < Nrows) {
                float2 v = make_float2(acc[i][j][2] + bx, acc[i][j][3] + by);
                *(float2*)(C + (size_t)r1 * ldC + col) = v;
            }
        }
    }
}

// ============================ launch ============================
extern "C" void kernel_launch(void* const* d_in, const int* in_sizes, int n_in,
                              void* d_out, int out_size) {
    const float* x    = (const float*)d_in[0];
    const int*   ei   = (const int*)d_in[1];
    const int*   eli  = (const int*)d_in[2];
    const float* cut  = (const float*)d_in[3];
    const float* W1   = (const float*)d_in[4];
    const float* b1   = (const float*)d_in[5];
    const float* bng  = (const float*)d_in[6];
    const float* bnb  = (const float*)d_in[7];
    const float* W2   = (const float*)d_in[8];
    const float* b2   = (const float*)d_in[9];
    const float* lng  = (const float*)d_in[10];
    const float* lnb  = (const float*)d_in[11];
    const float* linW = (const float*)d_in[12];
    const float* linb = (const float*)d_in[13];

    int N  = in_sizes[0] / 128;
    int E  = in_sizes[1] / 2;
    int EL = in_sizes[2] / 2;
    const int* src = ei;
    const int* dst = ei + E;
    const int* la  = eli;
    const int* lb  = eli + EL;
    float* out = (float*)d_out;

    void* p;
    float *deg, *xa, *h1, *t, *h2, *z, *bsum, *bsq, *bsc, *bsh;
    float *w1h, *w1l, *w2h, *w2l, *w3h, *w3l;
    cudaGetSymbolAddress(&p, g_deg);     deg  = (float*)p;
    cudaGetSymbolAddress(&p, g_xa);      xa   = (float*)p;
    cudaGetSymbolAddress(&p, g_h1);      h1   = (float*)p;
    cudaGetSymbolAddress(&p, g_t);       t    = (float*)p;
    cudaGetSymbolAddress(&p, g_h2);      h2   = (float*)p;
    cudaGetSymbolAddress(&p, g_z);       z    = (float*)p;
    cudaGetSymbolAddress(&p, g_bnsum);   bsum = (float*)p;
    cudaGetSymbolAddress(&p, g_bnsumsq); bsq  = (float*)p;
    cudaGetSymbolAddress(&p, g_bnsc);    bsc  = (float*)p;
    cudaGetSymbolAddress(&p, g_bnsh);    bsh  = (float*)p;
    cudaGetSymbolAddress(&p, g_w1t_hi);  w1h  = (float*)p;
    cudaGetSymbolAddress(&p, g_w1t_lo);  w1l  = (float*)p;
    cudaGetSymbolAddress(&p, g_w2t_hi);  w2h  = (float*)p;
    cudaGetSymbolAddress(&p, g_w2t_lo);  w2l  = (float*)p;
    cudaGetSymbolAddress(&p, g_w3t_hi);  w3h  = (float*)p;
    cudaGetSymbolAddress(&p, g_w3t_lo);  w3l  = (float*)p;

    constexpr int SMEMSZ = 4 * 128 * 36 * 4;  // 73728 B
    cudaFuncSetAttribute(mm_gemm_kernel<128, false, true>,
                         cudaFuncAttributeMaxDynamicSharedMemorySize, SMEMSZ);
    cudaFuncSetAttribute(mm_gemm_kernel<256, true, false>,
                         cudaFuncAttributeMaxDynamicSharedMemorySize, SMEMSZ);

    cudaMemsetAsync(deg, 0, (size_t)N * sizeof(float));
    cudaMemsetAsync(xa,  0, (size_t)N * 128 * sizeof(float));
    cudaMemsetAsync(h2,  0, (size_t)N * 128 * sizeof(float));
    cudaMemsetAsync(bsum, 0, 256 * sizeof(float));
    cudaMemsetAsync(bsq,  0, 256 * sizeof(float));

    // pre-split weights (tiny)
    wsplit_kernel<<<(128 * 256 + 255) / 256, 256>>>(W1, w1h, w1l, 128, 256);
    wsplit_kernel<<<(256 * 128 + 255) / 256, 256>>>(W2, w2h, w2l, 256, 128);
    wsplit_kernel<<<(128 * 128 + 255) / 256, 256>>>(linW, w3h, w3l, 128, 128);

    // degree + dinv
    deg_kernel<<<(E + 255) / 256, 256>>>(deg, dst, E);
    dinv_kernel<<<(N + 255) / 256, 256>>>(deg, N);

    int tiles = (N + 127) / 128;

    // layer 1: aggregate x, then GEMM1 (+b1), NOUT=256 via 2 column tiles
    agg_kernel<<<(E + 7) / 8, 256>>>(x, xa, src, dst, E, deg);
    selfloop_kernel<<<((size_t)N * 32 + 255) / 256, 256>>>(x, deg, xa, N);
    mm_gemm_kernel<128, false, true><<<dim3(tiles, 2), 256, SMEMSZ>>>(
        xa, w1h, w1l, b1, nullptr, nullptr, h1, N, 256);

    // BatchNorm stats
    colstats_kernel<<<(N + 255) / 256, 256>>>(h1, bsum, bsq, N);
    bnfinal_kernel<<<1, 256>>>(bsum, bsq, bng, bnb, bsc, bsh, N);

    // layer 2: GEMM2 with fused BN+ReLU on A, then aggregate
    mm_gemm_kernel<256, true, false><<<dim3(tiles, 1), 256, SMEMSZ>>>(
        h1, w2h, w2l, nullptr, bsc, bsh, t, N, 128);
    agg_kernel<<<(E + 7) / 8, 256>>>(t, h2, src, dst, E, deg);

    // self-loop + bias + LayerNorm + ReLU -> xa
    ln_kernel<<<((size_t)N * 32 + 255) / 256, 256>>>(h2, t, deg, b2, lng, lnb, xa, N);

    // final linear (+linb)
    mm_gemm_kernel<128, false, true><<<dim3(tiles, 1), 256, SMEMSZ>>>(
        xa, w3h, w3l, linb, nullptr, nullptr, z, N, 128);

    // decode
    int writeRound = (out_size >= 2 * EL) ? 1 : 0;
    decode_kernel<<<((size_t)EL + 7) / 8, 256>>>(z, la, lb, cut, out, EL, writeRound);
}